// round 2
// baseline (speedup 1.0000x reference)
#include <cuda_runtime.h>
#include <cstdint>

// Dims: Nt=64, Nr=64, Mt=32, Mr=32, G^2=4096, num_sc=32, B=64, R=8, N_r_RF=4
#define G2 4096
typedef unsigned long long u64;

// ---- device globals (no allocation allowed) ----
// Dual-form coefficient tables (built in setup):
//   g_W4c[d*32+m] = (w.x, w.x, w.y, -w.y)   -> conj(w)*h form
//   g_F4c[c*32+a] = (f.x, f.x, -f.y, f.y)   -> f*s form
__device__ float4 g_W4c[2048];
__device__ float4 g_F4c[2048];
__device__ float2 g_G1[(size_t)64 * 32 * 64 * 32];   // G1[b][m][c][s], 32 MB

// ---- f32x2 packed math helpers ----
__device__ __forceinline__ u64 ffma2(u64 a, u64 b, u64 c) {
    u64 d; asm("fma.rn.f32x2 %0,%1,%2,%3;" : "=l"(d) : "l"(a), "l"(b), "l"(c)); return d;
}
__device__ __forceinline__ u64 fadd2(u64 a, u64 b) {
    u64 d; asm("add.rn.f32x2 %0,%1,%2;" : "=l"(d) : "l"(a), "l"(b)); return d;
}
__device__ __forceinline__ u64 swap2(u64 v) {
    uint2 t; asm("mov.b64 {%0,%1},%2;" : "=r"(t.x), "=r"(t.y) : "l"(v));
    u64 r;  asm("mov.b64 %0,{%1,%2};" : "=l"(r) : "r"(t.y), "r"(t.x));
    return r;
}
__device__ __forceinline__ uint32_t saddr(const void* p) {
    return (uint32_t)__cvta_generic_to_shared(p);
}
__device__ __forceinline__ void lds_v2(u64& a, u64& b, uint32_t addr) {
    asm volatile("ld.shared.v2.b64 {%0,%1},[%2];" : "=l"(a), "=l"(b) : "r"(addr));
}
__device__ __forceinline__ u64 lds_1(uint32_t addr) {
    u64 a; asm volatile("ld.shared.b64 %0,[%1];" : "=l"(a) : "r"(addr)); return a;
}
__device__ __forceinline__ void sts_v2(uint32_t addr, u64 a, u64 b) {
    asm volatile("st.shared.v2.b64 [%0],{%1,%2};" :: "r"(addr), "l"(a), "l"(b));
}
__device__ __forceinline__ void sts_1(uint32_t addr, u64 a) {
    asm volatile("st.shared.b64 [%0],%1;" :: "r"(addr), "l"(a));
}
__device__ __forceinline__ void ldg_v2(u64& a, u64& b, const void* p) {
    asm("ld.global.nc.v2.b64 {%0,%1},[%2];" : "=l"(a), "=l"(b) : "l"(p));
}
__device__ __forceinline__ u64 ldg_1(const void* p) {
    u64 a; asm("ld.global.nc.b64 %0,[%1];" : "=l"(a) : "l"(p)); return a;
}
__device__ __forceinline__ void stg_v2(void* p, u64 a, u64 b) {
    asm volatile("st.global.v2.b64 [%0],{%1,%2};" :: "l"(p), "l"(a), "l"(b));
}
__device__ __forceinline__ void stg_1(void* p, u64 a) {
    asm volatile("st.global.b64 [%0],%1;" :: "l"(p), "l"(a));
}

// ---- setup: build dual-form tables ----
__global__ void setup_kernel(const float* __restrict__ kW, const float* __restrict__ kF) {
    int i = blockIdx.x * blockDim.x + threadIdx.x;
    if (i < 2048) {
        float s, c;
        sincosf(kW[i], &s, &c);
        c *= 0.125f; s *= 0.125f;                       // 1/sqrt(64)
        g_W4c[i] = make_float4(c, c, s, -s);            // (wxx | wyn)
        sincosf(kF[i], &s, &c);
        c *= 0.125f; s *= 0.125f;
        g_F4c[i] = make_float4(c, c, -s, s);            // (fxx | fyn)
    }
}

// =====================================================================
// Phi[a*32+bp, g] = sum_c F[c,a] * ( sum_d conj(W[d,bp]) * K[c*64+d, g] )
// Block: 8 g columns. 256 threads, 8 warps. Warp w owns d in [8w,8w+8)
// with its W slice held in registers (dual form). Partial sums reduced
// through shared, then F-combined into register Phi accumulators.
// =====================================================================
__global__ void __launch_bounds__(256, 2) phi_kernel(const float4* __restrict__ K4,
                                                     float2* __restrict__ Phi) {
    __shared__ float4 Kt4[64 * 8];   // 8KB  [d*8+g] = (h.x,h.y,h.y,h.x)
    __shared__ u64    Ps[8 * 8 * 32];// 16KB [g][w][bp]
    __shared__ float4 Ss4[8 * 32];   // 4KB  [g*32+bp] = (s.x,s.y,s.y,s.x)

    const int t = threadIdx.x;
    const int lane = t & 31, wrp = t >> 5;
    const int g0 = blockIdx.x * 8;

    // register W dual forms: d = wrp*8 + i, bp = lane
    u64 wxx[8], wyn[8];
#pragma unroll
    for (int i = 0; i < 8; ++i)
        ldg_v2(wxx[i], wyn[i], &g_W4c[(wrp * 8 + i) * 32 + lane]);

    // staging mapping: thread -> (row d = t>>2, float4 col sgq = t&3)
    const int sd = t >> 2, sgq = t & 3;
    const float4* Kp = K4 + (size_t)sd * 2048 + (g0 >> 1) + sgq;
    const uint32_t ktw = saddr(Kt4) + (uint32_t)(sd * 8 + sgq * 2) * 16;

    const uint32_t kt0 = saddr(Kt4) + (uint32_t)wrp * 1024;   // S-phase read base
    const uint32_t psw = saddr(Ps) + (uint32_t)(wrp * 32 + lane) * 8;   // partial write
    const uint32_t psr = saddr(Ps) + (uint32_t)wrp * 2048 + (uint32_t)lane * 8; // reduce read
    const uint32_t ssw = saddr(Ss4) + (uint32_t)t * 16;       // reduce write
    const uint32_t ssr = saddr(Ss4) + (uint32_t)lane * 16;    // Phi-phase read base

    u64 acc[4][8];
#pragma unroll
    for (int a = 0; a < 4; ++a)
#pragma unroll
        for (int g = 0; g < 8; ++g) acc[a][g] = 0ull;

    u64 q0, q1;
    ldg_v2(q0, q1, Kp);   // prefetch c = 0

    for (int c = 0; c < 64; ++c) {
        __syncthreads();                       // Ss4 reads done (prev Phi phase)
        sts_v2(ktw, q0, swap2(q0));            // stage expanded K tile
        sts_v2(ktw + 16, q1, swap2(q1));
        __syncthreads();
        if (c < 63) ldg_v2(q0, q1, Kp + (size_t)(c + 1) * 131072);  // prefetch next c

        // ---- S-phase: d-partial sums (register W, broadcast K) ----
        u64 part[8];
#pragma unroll
        for (int g = 0; g < 8; ++g) part[g] = 0ull;
#pragma unroll
        for (int i = 0; i < 8; ++i) {
#pragma unroll
            for (int g = 0; g < 8; ++g) {
                u64 kq, kqs;
                lds_v2(kq, kqs, kt0 + (uint32_t)(i * 128 + g * 16));
                part[g] = ffma2(wyn[i], kqs, ffma2(wxx[i], kq, part[g]));
            }
        }
#pragma unroll
        for (int g = 0; g < 8; ++g) sts_1(psw + (uint32_t)g * 2048, part[g]);
        __syncthreads();

        // ---- reduce: S[g=wrp][bp=lane] = sum_w partial ----
        {
            u64 s = lds_1(psr);
#pragma unroll
            for (int w = 1; w < 8; ++w) s = fadd2(s, lds_1(psr + (uint32_t)w * 256));
            sts_v2(ssw, s, swap2(s));
        }
        __syncthreads();

        // ---- Phi-phase: acc[a][g] += F[c, wrp*4+aa] * S[g][lane] ----
        u64 fxx[4], fyn[4];
#pragma unroll
        for (int aa = 0; aa < 4; ++aa)
            ldg_v2(fxx[aa], fyn[aa], &g_F4c[c * 32 + wrp * 4 + aa]);
#pragma unroll
        for (int g = 0; g < 8; ++g) {
            u64 sq, sqs;
            lds_v2(sq, sqs, ssr + (uint32_t)g * 512);
#pragma unroll
            for (int aa = 0; aa < 4; ++aa)
                acc[aa][g] = ffma2(fyn[aa], sqs, ffma2(fxx[aa], sq, acc[aa][g]));
        }
    }

    // write Phi: q = (wrp*4+aa)*32 + lane, 8 g values = 4 x 16B
#pragma unroll
    for (int aa = 0; aa < 4; ++aa) {
        float2* dst = Phi + (size_t)((wrp * 4 + aa) * 32 + lane) * G2 + g0;
#pragma unroll
        for (int g = 0; g < 8; g += 2)
            stg_v2(dst + g, acc[aa][g], acc[aa][g + 1]);
    }
}

// =====================================================================
// G1[b][m][c][s] = sum_d conj(W[d][m]) * H[b][d][c][s]
// =====================================================================
__global__ void __launch_bounds__(256) y1_kernel(const float2* __restrict__ H) {
    __shared__ float4 Ws4[2048];   // 32KB dual-form W
    const int t = threadIdx.x;
    for (int i = t; i < 2048; i += 256) Ws4[i] = g_W4c[i];

    const int b = blockIdx.x >> 3, ct = blockIdx.x & 7;
    const int s = t & 31, cl = t >> 5, c = ct * 8 + cl;
    const float2* Hp = H + ((size_t)b * 4096 + c) * 32 + s;
    const uint32_t ws = saddr(Ws4);

    u64 acc[32];
#pragma unroll
    for (int m = 0; m < 32; ++m) acc[m] = 0ull;
    __syncthreads();

    for (int d = 0; d < 64; d += 2) {
        u64 h0 = ldg_1(Hp + (size_t)d * 2048);
        u64 h1 = ldg_1(Hp + (size_t)(d + 1) * 2048);
        u64 h0s = swap2(h0), h1s = swap2(h1);
#pragma unroll
        for (int m = 0; m < 32; ++m) {
            u64 wxx, wyn;
            lds_v2(wxx, wyn, ws + (uint32_t)((d * 32 + m) << 4));
            acc[m] = ffma2(wyn, h0s, ffma2(wxx, h0, acc[m]));
            lds_v2(wxx, wyn, ws + (uint32_t)(((d + 1) * 32 + m) << 4));
            acc[m] = ffma2(wyn, h1s, ffma2(wxx, h1, acc[m]));
        }
    }

    float2* Gp = g_G1 + (size_t)b * 65536 + (size_t)c * 32 + s;
#pragma unroll
    for (int m = 0; m < 32; ++m) stg_1(Gp + (size_t)m * 2048, acc[m]);
}

// =====================================================================
// y[b, a*32 + (4r+j), s] = sum_c F[c,a]*G1[b,4r+j,c,s]
//                        + sum_n conj(W[n,4r+j])*noise[b,r,n, a*32+s]
// Block = (b, r, half-of-x). Thread owns 2 consecutive x and 4 j.
// =====================================================================
__global__ void __launch_bounds__(256) y2_kernel(const float4* __restrict__ noise4,
                                                 float2* __restrict__ Y) {
    __shared__ float4 Wn4[256];    // dual forms for m = r*4+j
    const int t = threadIdx.x;
    const int b = blockIdx.x >> 4, r = (blockIdx.x >> 1) & 7, half = blockIdx.x & 1;
    {
        int n = t >> 2, j = t & 3;
        Wn4[t] = g_W4c[n * 32 + r * 4 + j];
    }
    __syncthreads();

    const int x0 = half * 512 + t * 2;
    const int s = x0 & 31, a = x0 >> 5;
    const uint32_t wn = saddr(Wn4);

    u64 acc[4][2];
#pragma unroll
    for (int j = 0; j < 4; ++j) { acc[j][0] = 0ull; acc[j][1] = 0ull; }

    // ---- noise term: stream 256KB/block, fully coalesced float4 ----
    const float4* np = noise4 + (size_t)(b * 8 + r) * 32768 + (x0 >> 1);
#pragma unroll 4
    for (int n = 0; n < 64; ++n) {
        u64 v0, v1;
        ldg_v2(v0, v1, np + (size_t)n * 512);
        u64 v0s = swap2(v0), v1s = swap2(v1);
#pragma unroll
        for (int j = 0; j < 4; ++j) {
            u64 wxx, wyn;
            lds_v2(wxx, wyn, wn + (uint32_t)((n * 4 + j) << 4));
            acc[j][0] = ffma2(wyn, v0s, ffma2(wxx, v0, acc[j][0]));
            acc[j][1] = ffma2(wyn, v1s, ffma2(wxx, v1, acc[j][1]));
        }
    }

    // ---- signal term: contract G1 over c with F ----
    const float4* gp = (const float4*)g_G1 + ((size_t)b * 32 + r * 4) * 1024 + (s >> 1);
#pragma unroll 2
    for (int c = 0; c < 64; ++c) {
        u64 fxx, fyn;
        ldg_v2(fxx, fyn, &g_F4c[c * 32 + a]);
#pragma unroll
        for (int j = 0; j < 4; ++j) {
            u64 g0v, g1v;
            ldg_v2(g0v, g1v, gp + (size_t)j * 1024 + c * 16);
            acc[j][0] = ffma2(fyn, swap2(g0v), ffma2(fxx, g0v, acc[j][0]));
            acc[j][1] = ffma2(fyn, swap2(g1v), ffma2(fxx, g1v, acc[j][1]));
        }
    }

    // write y[b][a*32 + r*4 + j][s..s+1]
#pragma unroll
    for (int j = 0; j < 4; ++j) {
        float2* yp = Y + ((size_t)b * 1024 + a * 32 + r * 4 + j) * 32 + s;
        stg_v2(yp, acc[j][0], acc[j][1]);
    }
}

extern "C" void kernel_launch(void* const* d_in, const int* in_sizes, int n_in,
                              void* d_out, int out_size) {
    const float2* H     = (const float2*)d_in[0];  // (64,64,64,32,2) f32
    const float4* noise = (const float4*)d_in[1];  // (64,8,64,1024,2) f32
    const float*  kW    = (const float*)d_in[2];   // (64,32)
    const float*  kF    = (const float*)d_in[3];   // (64,32)
    const float4* K4    = (const float4*)d_in[4];  // (4096,4096,2)

    float2* Phi = (float2*)d_out;                   // 1024*4096 complex
    float2* Y   = Phi + (size_t)1024 * 4096;        // 64*1024*32 complex

    setup_kernel<<<8, 256>>>(kW, kF);
    phi_kernel<<<512, 256>>>(K4, Phi);
    y1_kernel<<<512, 256>>>(H);
    y2_kernel<<<1024, 256>>>(noise, Y);
}

// round 3
// speedup vs baseline: 1.4790x; 1.4790x over previous
#include <cuda_runtime.h>
#include <cstdint>

// Dims: Nt=64, Nr=64, Mt=32, Mr=32, G^2=4096, num_sc=32, B=64, R=8, N_r_RF=4
#define G2 4096
typedef unsigned long long u64;

// ---- device globals (no allocation allowed) ----
// Dual-form coefficient tables:
//   g_W4c[d*32+m] = (w.x, w.x, w.y, -w.y)   -> conj(w)*h
//   g_F4c[c*32+a] = (f.x, f.x, -f.y, f.y)   -> f*s
__device__ float4 g_W4c[2048];
__device__ float4 g_F4c[2048];
__device__ float2 g_S [(size_t)2048 * 4096];        // S[c*32+bp][g], 64 MB
__device__ float2 g_G1[(size_t)2048 * 2048];        // G1[b*32+m][c*32+s], 32 MB

// ---- f32x2 packed helpers ----
__device__ __forceinline__ u64 ffma2(u64 a, u64 b, u64 c) {
    u64 d; asm("fma.rn.f32x2 %0,%1,%2,%3;" : "=l"(d) : "l"(a), "l"(b), "l"(c)); return d;
}
__device__ __forceinline__ u64 swap2(u64 v) {
    uint2 t; asm("mov.b64 {%0,%1},%2;" : "=r"(t.x), "=r"(t.y) : "l"(v));
    u64 r;  asm("mov.b64 %0,{%1,%2};" : "=l"(r) : "r"(t.y), "r"(t.x));
    return r;
}
__device__ __forceinline__ uint32_t saddr(const void* p) {
    return (uint32_t)__cvta_generic_to_shared(p);
}
__device__ __forceinline__ void lds_v2(u64& a, u64& b, uint32_t addr) {
    asm volatile("ld.shared.v2.b64 {%0,%1},[%2];" : "=l"(a), "=l"(b) : "r"(addr));
}
__device__ __forceinline__ void ldg_v2(u64& a, u64& b, const void* p) {
    asm("ld.global.nc.v2.b64 {%0,%1},[%2];" : "=l"(a), "=l"(b) : "l"(p));
}
__device__ __forceinline__ void ldg_v2_c(u64& a, u64& b, const void* p) {   // coherent
    asm volatile("ld.global.v2.b64 {%0,%1},[%2];" : "=l"(a), "=l"(b) : "l"(p));
}
__device__ __forceinline__ void stg_v2(void* p, u64 a, u64 b) {
    asm volatile("st.global.v2.b64 [%0],{%1,%2};" :: "l"(p), "l"(a), "l"(b));
}
__device__ __forceinline__ u64 fadd2(u64 a, u64 b) {
    u64 d; asm("add.rn.f32x2 %0,%1,%2;" : "=l"(d) : "l"(a), "l"(b)); return d;
}

// ---- setup: dual-form tables ----
__global__ void setup_kernel(const float* __restrict__ kW, const float* __restrict__ kF) {
    int i = blockIdx.x * blockDim.x + threadIdx.x;
    if (i < 2048) {
        float s, c;
        sincosf(kW[i], &s, &c);
        c *= 0.125f; s *= 0.125f;
        g_W4c[i] = make_float4(c, c, s, -s);
        sincosf(kF[i], &s, &c);
        c *= 0.125f; s *= 0.125f;
        g_F4c[i] = make_float4(c, c, -s, s);
    }
}

// =====================================================================
// passA: S[c][bp][g] = sum_d conj(W[d,bp]) * K[c*64+d, g]
// grid 2048 = (c, g-tile 128); 256 thr; thread tile 8bp x 2g.
// =====================================================================
__global__ void __launch_bounds__(256) sA_kernel(const float2* __restrict__ K) {
    __shared__ float4 Wt[2048];
    const int t = threadIdx.x;
#pragma unroll
    for (int i = 0; i < 8; ++i) Wt[t + 256 * i] = g_W4c[t + 256 * i];
    __syncthreads();

    const int c  = blockIdx.x >> 5, gt = blockIdx.x & 31;
    const int gp = t & 63, bg = t >> 6;
    const int g  = gt * 128 + gp * 2;

    const float2* Kp = K + (size_t)(c * 64) * G2 + g;
    const uint32_t wbase = saddr(Wt) + (uint32_t)(bg * 8) * 16;

    u64 acc0[8], acc1[8];
#pragma unroll
    for (int i = 0; i < 8; ++i) { acc0[i] = 0ull; acc1[i] = 0ull; }

    u64 ka0, ka1, kb0, kb1;
    ldg_v2(ka0, ka1, Kp);
    ldg_v2(kb0, kb1, Kp + G2);

#pragma unroll 2
    for (int d = 0; d < 64; ++d) {
        u64 kc0 = 0, kc1 = 0;
        if (d + 2 < 64) ldg_v2(kc0, kc1, Kp + (size_t)(d + 2) * G2);
        const u64 s0 = swap2(ka0), s1 = swap2(ka1);
        const uint32_t wa = wbase + (uint32_t)d * 512;
#pragma unroll
        for (int i = 0; i < 8; ++i) {
            u64 wxx, wyn;
            lds_v2(wxx, wyn, wa + i * 16);
            acc0[i] = ffma2(wyn, s0, ffma2(wxx, ka0, acc0[i]));
            acc1[i] = ffma2(wyn, s1, ffma2(wxx, ka1, acc1[i]));
        }
        ka0 = kb0; ka1 = kb1; kb0 = kc0; kb1 = kc1;
    }

    float2* Sp = g_S + (size_t)(c * 32 + bg * 8) * G2 + g;
#pragma unroll
    for (int i = 0; i < 8; ++i) stg_v2(Sp + (size_t)i * G2, acc0[i], acc1[i]);
}

// =====================================================================
// passB: Phi[(a*32+bp)][g] = sum_c F[c,a] * S[c][bp][g]
// grid 1024 = (bp, g-tile 128); thread tile 8a x 2g.
// =====================================================================
__global__ void __launch_bounds__(256) phiB_kernel(float2* __restrict__ Phi) {
    __shared__ float4 Ft[2048];
    const int t = threadIdx.x;
#pragma unroll
    for (int i = 0; i < 8; ++i) Ft[t + 256 * i] = g_F4c[t + 256 * i];
    __syncthreads();

    const int bp = blockIdx.x >> 5, gt = blockIdx.x & 31;
    const int gp = t & 63, ag = t >> 6;
    const int g  = gt * 128 + gp * 2;

    const float2* Sp = g_S + (size_t)bp * G2 + g;          // + c*32*G2
    const uint32_t fbase = saddr(Ft) + (uint32_t)(ag * 8) * 16;

    u64 acc0[8], acc1[8];
#pragma unroll
    for (int i = 0; i < 8; ++i) { acc0[i] = 0ull; acc1[i] = 0ull; }

    u64 ka0, ka1, kb0, kb1;
    ldg_v2(ka0, ka1, Sp);
    ldg_v2(kb0, kb1, Sp + (size_t)32 * G2);

#pragma unroll 2
    for (int c = 0; c < 64; ++c) {
        u64 kc0 = 0, kc1 = 0;
        if (c + 2 < 64) ldg_v2(kc0, kc1, Sp + (size_t)(c + 2) * 32 * G2);
        const u64 s0 = swap2(ka0), s1 = swap2(ka1);
        const uint32_t fa = fbase + (uint32_t)c * 512;
#pragma unroll
        for (int i = 0; i < 8; ++i) {
            u64 fxx, fyn;
            lds_v2(fxx, fyn, fa + i * 16);
            acc0[i] = ffma2(fyn, s0, ffma2(fxx, ka0, acc0[i]));
            acc1[i] = ffma2(fyn, s1, ffma2(fxx, ka1, acc1[i]));
        }
        ka0 = kb0; ka1 = kb1; kb0 = kc0; kb1 = kc1;
    }

    float2* Pp = Phi + (size_t)(ag * 8 * 32 + bp) * G2 + g;
#pragma unroll
    for (int i = 0; i < 8; ++i) stg_v2(Pp + (size_t)(i * 32) * G2, acc0[i], acc1[i]);
}

// =====================================================================
// y1: G1[b*32+m][cs] = sum_d conj(W[d,m]) * H[b][d][cs]   (cs = c*32+s)
// grid 1024 = (b, cs-tile 128); thread tile 8m x 2cs.
// =====================================================================
__global__ void __launch_bounds__(256) y1_kernel(const float2* __restrict__ H) {
    __shared__ float4 Wt[2048];
    const int t = threadIdx.x;
#pragma unroll
    for (int i = 0; i < 8; ++i) Wt[t + 256 * i] = g_W4c[t + 256 * i];
    __syncthreads();

    const int b   = blockIdx.x >> 4, cst = blockIdx.x & 15;
    const int csp = t & 63, mg = t >> 6;
    const int cs  = cst * 128 + csp * 2;

    const float2* Hp = H + (size_t)b * 131072 + cs;        // + d*2048
    const uint32_t wbase = saddr(Wt) + (uint32_t)(mg * 8) * 16;

    u64 acc0[8], acc1[8];
#pragma unroll
    for (int i = 0; i < 8; ++i) { acc0[i] = 0ull; acc1[i] = 0ull; }

    u64 ka0, ka1, kb0, kb1;
    ldg_v2(ka0, ka1, Hp);
    ldg_v2(kb0, kb1, Hp + 2048);

#pragma unroll 2
    for (int d = 0; d < 64; ++d) {
        u64 kc0 = 0, kc1 = 0;
        if (d + 2 < 64) ldg_v2(kc0, kc1, Hp + (size_t)(d + 2) * 2048);
        const u64 s0 = swap2(ka0), s1 = swap2(ka1);
        const uint32_t wa = wbase + (uint32_t)d * 512;
#pragma unroll
        for (int i = 0; i < 8; ++i) {
            u64 wxx, wyn;
            lds_v2(wxx, wyn, wa + i * 16);
            acc0[i] = ffma2(wyn, s0, ffma2(wxx, ka0, acc0[i]));
            acc1[i] = ffma2(wyn, s1, ffma2(wxx, ka1, acc1[i]));
        }
        ka0 = kb0; ka1 = kb1; kb0 = kc0; kb1 = kc1;
    }

    float2* Gp = g_G1 + (size_t)(b * 32 + mg * 8) * 2048 + cs;
#pragma unroll
    for (int i = 0; i < 8; ++i) stg_v2(Gp + (size_t)i * 2048, acc0[i], acc1[i]);
}

// =====================================================================
// y2s: Y[b][(a*32+m)][s] = sum_c F[c,a] * G1[b*32+m][c*32+s]
// grid 512: 4 (b,m) per block; per (b,m): 64 thr = 16 s-pairs x 4 a-grps,
// thread tile 8a x 2s.
// =====================================================================
__global__ void __launch_bounds__(256) y2s_kernel(float2* __restrict__ Y) {
    __shared__ float4 Ft[2048];
    const int t = threadIdx.x;
#pragma unroll
    for (int i = 0; i < 8; ++i) Ft[t + 256 * i] = g_F4c[t + 256 * i];
    __syncthreads();

    const int bm = blockIdx.x * 4 + (t >> 6);
    const int b  = bm >> 5, m = bm & 31;
    const int sp = t & 15, ag = (t >> 4) & 3;
    const int s  = sp * 2;

    const float2* Gp = g_G1 + (size_t)bm * 2048 + s;       // + c*32
    const uint32_t fbase = saddr(Ft) + (uint32_t)(ag * 8) * 16;

    u64 acc0[8], acc1[8];
#pragma unroll
    for (int i = 0; i < 8; ++i) { acc0[i] = 0ull; acc1[i] = 0ull; }

    u64 ka0, ka1, kb0, kb1;
    ldg_v2(ka0, ka1, Gp);
    ldg_v2(kb0, kb1, Gp + 32);

#pragma unroll 2
    for (int c = 0; c < 64; ++c) {
        u64 kc0 = 0, kc1 = 0;
        if (c + 2 < 64) ldg_v2(kc0, kc1, Gp + (size_t)(c + 2) * 32);
        const u64 s0 = swap2(ka0), s1 = swap2(ka1);
        const uint32_t fa = fbase + (uint32_t)c * 512;
#pragma unroll
        for (int i = 0; i < 8; ++i) {
            u64 fxx, fyn;
            lds_v2(fxx, fyn, fa + i * 16);
            acc0[i] = ffma2(fyn, s0, ffma2(fxx, ka0, acc0[i]));
            acc1[i] = ffma2(fyn, s1, ffma2(fxx, ka1, acc1[i]));
        }
        ka0 = kb0; ka1 = kb1; kb0 = kc0; kb1 = kc1;
    }

#pragma unroll
    for (int i = 0; i < 8; ++i) {
        float2* yp = Y + (size_t)(b * 1024 + (ag * 8 + i) * 32 + m) * 32 + s;
        stg_v2(yp, acc0[i], acc1[i]);
    }
}

// =====================================================================
// y2n: Y[b][a*32 + r*4 + j][s] += sum_n conj(W[n, r*4+j]) * noise[b,r,n,x]
// x = a*32+s. grid 512 = (b,r); thread owns x-quad x0=t*4, 4 j.
// Pure 256MB DRAM stream + small RMW tail.
// =====================================================================
__global__ void __launch_bounds__(256) y2n_kernel(const float2* __restrict__ noise,
                                                  float2* __restrict__ Y) {
    __shared__ float4 Wn[256];   // [n*4+j]
    const int t = threadIdx.x;
    const int b = blockIdx.x >> 3, r = blockIdx.x & 7;
    Wn[t] = g_W4c[(t >> 2) * 32 + r * 4 + (t & 3)];
    __syncthreads();

    const int x0 = t * 4;
    const uint32_t wn = saddr(Wn);
    const float2* np = noise + (size_t)(b * 8 + r) * 65536 + x0;

    u64 acc[4][4];
#pragma unroll
    for (int j = 0; j < 4; ++j)
#pragma unroll
        for (int k = 0; k < 4; ++k) acc[j][k] = 0ull;

#pragma unroll 4
    for (int n = 0; n < 64; ++n) {
        u64 v0, v1, v2, v3;
        ldg_v2(v0, v1, np + (size_t)n * 1024);
        ldg_v2(v2, v3, np + (size_t)n * 1024 + 2);
        const u64 w0 = swap2(v0), w1 = swap2(v1), w2 = swap2(v2), w3 = swap2(v3);
#pragma unroll
        for (int j = 0; j < 4; ++j) {
            u64 wxx, wyn;
            lds_v2(wxx, wyn, wn + (uint32_t)((n * 4 + j) << 4));
            acc[j][0] = ffma2(wyn, w0, ffma2(wxx, v0, acc[j][0]));
            acc[j][1] = ffma2(wyn, w1, ffma2(wxx, v1, acc[j][1]));
            acc[j][2] = ffma2(wyn, w2, ffma2(wxx, v2, acc[j][2]));
            acc[j][3] = ffma2(wyn, w3, ffma2(wxx, v3, acc[j][3]));
        }
    }

    const int a = x0 >> 5, s = x0 & 31;
#pragma unroll
    for (int j = 0; j < 4; ++j) {
        float2* yp = Y + (size_t)(b * 1024 + a * 32 + r * 4 + j) * 32 + s;
        u64 y0, y1, y2, y3;
        ldg_v2_c(y0, y1, yp);
        ldg_v2_c(y2, y3, yp + 2);
        stg_v2(yp,     fadd2(y0, acc[j][0]), fadd2(y1, acc[j][1]));
        stg_v2(yp + 2, fadd2(y2, acc[j][2]), fadd2(y3, acc[j][3]));
    }
}

extern "C" void kernel_launch(void* const* d_in, const int* in_sizes, int n_in,
                              void* d_out, int out_size) {
    const float2* H     = (const float2*)d_in[0];  // (64,64,64,32,2) f32
    const float2* noise = (const float2*)d_in[1];  // (64,8,64,1024,2) f32
    const float*  kW    = (const float*)d_in[2];   // (64,32)
    const float*  kF    = (const float*)d_in[3];   // (64,32)
    const float2* K     = (const float2*)d_in[4];  // (4096,4096,2)

    float2* Phi = (float2*)d_out;                   // 1024*4096 complex
    float2* Y   = Phi + (size_t)1024 * 4096;        // 64*1024*32 complex

    setup_kernel<<<8, 256>>>(kW, kF);
    sA_kernel  <<<2048, 256>>>(K);
    y1_kernel  <<<1024, 256>>>(H);
    phiB_kernel<<<1024, 256>>>(Phi);
    y2s_kernel <<<512, 256>>>(Y);
    y2n_kernel <<<512, 256>>>(noise, Y);
}

// round 4
// speedup vs baseline: 1.4842x; 1.0035x over previous
#include <cuda_runtime.h>
#include <cstdint>

// Dims: Nt=64, Nr=64, Mt=32, Mr=32, G^2=4096, num_sc=32, B=64, R=8, N_r_RF=4
#define G2 4096
typedef unsigned long long u64;

// ---- device globals (no allocation allowed) ----
// Dual-form coefficient tables:
//   g_W4c[d*32+m] = (w.x, w.x, w.y, -w.y)   -> conj(w)*h
//   g_F4c[c*32+a] = (f.x, f.x, -f.y, f.y)   -> f*s
__device__ float4 g_W4c[2048];
__device__ float4 g_F4c[2048];
__device__ float2 g_S [(size_t)2048 * 4096];        // S[c*32+bp][g], 64 MB
__device__ float2 g_G1[(size_t)2048 * 2048];        // G1[b*32+m][c*32+s], 32 MB

// ---- f32x2 packed helpers ----
__device__ __forceinline__ u64 ffma2(u64 a, u64 b, u64 c) {
    u64 d; asm("fma.rn.f32x2 %0,%1,%2,%3;" : "=l"(d) : "l"(a), "l"(b), "l"(c)); return d;
}
__device__ __forceinline__ u64 swap2(u64 v) {
    uint2 t; asm("mov.b64 {%0,%1},%2;" : "=r"(t.x), "=r"(t.y) : "l"(v));
    u64 r;  asm("mov.b64 %0,{%1,%2};" : "=l"(r) : "r"(t.y), "r"(t.x));
    return r;
}
__device__ __forceinline__ uint32_t saddr(const void* p) {
    return (uint32_t)__cvta_generic_to_shared(p);
}
__device__ __forceinline__ void lds_v2(u64& a, u64& b, uint32_t addr) {
    asm volatile("ld.shared.v2.b64 {%0,%1},[%2];" : "=l"(a), "=l"(b) : "r"(addr));
}
__device__ __forceinline__ void ldg_v2(u64& a, u64& b, const void* p) {
    asm("ld.global.nc.v2.b64 {%0,%1},[%2];" : "=l"(a), "=l"(b) : "l"(p));
}
__device__ __forceinline__ void ldg_v2_c(u64& a, u64& b, const void* p) {   // coherent
    asm volatile("ld.global.v2.b64 {%0,%1},[%2];" : "=l"(a), "=l"(b) : "l"(p));
}
__device__ __forceinline__ void stg_v2(void* p, u64 a, u64 b) {
    asm volatile("st.global.v2.b64 [%0],{%1,%2};" :: "l"(p), "l"(a), "l"(b));
}
__device__ __forceinline__ u64 fadd2(u64 a, u64 b) {
    u64 d; asm("add.rn.f32x2 %0,%1,%2;" : "=l"(d) : "l"(a), "l"(b)); return d;
}

// ---- setup: dual-form tables ----
__global__ void setup_kernel(const float* __restrict__ kW, const float* __restrict__ kF) {
    int i = blockIdx.x * blockDim.x + threadIdx.x;
    if (i < 2048) {
        float s, c;
        sincosf(kW[i], &s, &c);
        c *= 0.125f; s *= 0.125f;
        g_W4c[i] = make_float4(c, c, s, -s);
        sincosf(kF[i], &s, &c);
        c *= 0.125f; s *= 0.125f;
        g_F4c[i] = make_float4(c, c, -s, s);
    }
}

// =====================================================================
// passA: S[c][bp][g] = sum_d conj(W[d,bp]) * K[c*64+d, g]
// grid 2048 = (c, g-tile 128); 256 thr; thread tile 8bp x 2g.
// =====================================================================
__global__ void __launch_bounds__(256) sA_kernel(const float2* __restrict__ K) {
    __shared__ float4 Wt[2048];
    const int t = threadIdx.x;
#pragma unroll
    for (int i = 0; i < 8; ++i) Wt[t + 256 * i] = g_W4c[t + 256 * i];
    __syncthreads();

    const int c  = blockIdx.x >> 5, gt = blockIdx.x & 31;
    const int gp = t & 63, bg = t >> 6;
    const int g  = gt * 128 + gp * 2;

    const float2* Kp = K + (size_t)(c * 64) * G2 + g;
    const uint32_t wbase = saddr(Wt) + (uint32_t)(bg * 8) * 16;

    u64 acc0[8], acc1[8];
#pragma unroll
    for (int i = 0; i < 8; ++i) { acc0[i] = 0ull; acc1[i] = 0ull; }

    u64 ka0, ka1, kb0, kb1;
    ldg_v2(ka0, ka1, Kp);
    ldg_v2(kb0, kb1, Kp + G2);

#pragma unroll 2
    for (int d = 0; d < 64; ++d) {
        u64 kc0 = 0, kc1 = 0;
        if (d + 2 < 64) ldg_v2(kc0, kc1, Kp + (size_t)(d + 2) * G2);
        const u64 s0 = swap2(ka0), s1 = swap2(ka1);
        const uint32_t wa = wbase + (uint32_t)d * 512;
#pragma unroll
        for (int i = 0; i < 8; ++i) {
            u64 wxx, wyn;
            lds_v2(wxx, wyn, wa + i * 16);
            acc0[i] = ffma2(wyn, s0, ffma2(wxx, ka0, acc0[i]));
            acc1[i] = ffma2(wyn, s1, ffma2(wxx, ka1, acc1[i]));
        }
        ka0 = kb0; ka1 = kb1; kb0 = kc0; kb1 = kc1;
    }

    float2* Sp = g_S + (size_t)(c * 32 + bg * 8) * G2 + g;
#pragma unroll
    for (int i = 0; i < 8; ++i) stg_v2(Sp + (size_t)i * G2, acc0[i], acc1[i]);
}

// =====================================================================
// passB: Phi[(a*32+bp)][g] = sum_c F[c,a] * S[c][bp][g]
// grid 1024 = (bp, g-tile 128); thread tile 8a x 2g.
// =====================================================================
__global__ void __launch_bounds__(256) phiB_kernel(float2* __restrict__ Phi) {
    __shared__ float4 Ft[2048];
    const int t = threadIdx.x;
#pragma unroll
    for (int i = 0; i < 8; ++i) Ft[t + 256 * i] = g_F4c[t + 256 * i];
    __syncthreads();

    const int bp = blockIdx.x >> 5, gt = blockIdx.x & 31;
    const int gp = t & 63, ag = t >> 6;
    const int g  = gt * 128 + gp * 2;

    const float2* Sp = g_S + (size_t)bp * G2 + g;          // + c*32*G2
    const uint32_t fbase = saddr(Ft) + (uint32_t)(ag * 8) * 16;

    u64 acc0[8], acc1[8];
#pragma unroll
    for (int i = 0; i < 8; ++i) { acc0[i] = 0ull; acc1[i] = 0ull; }

    u64 ka0, ka1, kb0, kb1;
    ldg_v2(ka0, ka1, Sp);
    ldg_v2(kb0, kb1, Sp + (size_t)32 * G2);

#pragma unroll 2
    for (int c = 0; c < 64; ++c) {
        u64 kc0 = 0, kc1 = 0;
        if (c + 2 < 64) ldg_v2(kc0, kc1, Sp + (size_t)(c + 2) * 32 * G2);
        const u64 s0 = swap2(ka0), s1 = swap2(ka1);
        const uint32_t fa = fbase + (uint32_t)c * 512;
#pragma unroll
        for (int i = 0; i < 8; ++i) {
            u64 fxx, fyn;
            lds_v2(fxx, fyn, fa + i * 16);
            acc0[i] = ffma2(fyn, s0, ffma2(fxx, ka0, acc0[i]));
            acc1[i] = ffma2(fyn, s1, ffma2(fxx, ka1, acc1[i]));
        }
        ka0 = kb0; ka1 = kb1; kb0 = kc0; kb1 = kc1;
    }

    float2* Pp = Phi + (size_t)(ag * 8 * 32 + bp) * G2 + g;
#pragma unroll
    for (int i = 0; i < 8; ++i) stg_v2(Pp + (size_t)(i * 32) * G2, acc0[i], acc1[i]);
}

// =====================================================================
// y1: G1[b*32+m][cs] = sum_d conj(W[d,m]) * H[b][d][cs]   (cs = c*32+s)
// grid 1024 = (b, cs-tile 128); thread tile 8m x 2cs.
// =====================================================================
__global__ void __launch_bounds__(256) y1_kernel(const float2* __restrict__ H) {
    __shared__ float4 Wt[2048];
    const int t = threadIdx.x;
#pragma unroll
    for (int i = 0; i < 8; ++i) Wt[t + 256 * i] = g_W4c[t + 256 * i];
    __syncthreads();

    const int b   = blockIdx.x >> 4, cst = blockIdx.x & 15;
    const int csp = t & 63, mg = t >> 6;
    const int cs  = cst * 128 + csp * 2;

    const float2* Hp = H + (size_t)b * 131072 + cs;        // + d*2048
    const uint32_t wbase = saddr(Wt) + (uint32_t)(mg * 8) * 16;

    u64 acc0[8], acc1[8];
#pragma unroll
    for (int i = 0; i < 8; ++i) { acc0[i] = 0ull; acc1[i] = 0ull; }

    u64 ka0, ka1, kb0, kb1;
    ldg_v2(ka0, ka1, Hp);
    ldg_v2(kb0, kb1, Hp + 2048);

#pragma unroll 2
    for (int d = 0; d < 64; ++d) {
        u64 kc0 = 0, kc1 = 0;
        if (d + 2 < 64) ldg_v2(kc0, kc1, Hp + (size_t)(d + 2) * 2048);
        const u64 s0 = swap2(ka0), s1 = swap2(ka1);
        const uint32_t wa = wbase + (uint32_t)d * 512;
#pragma unroll
        for (int i = 0; i < 8; ++i) {
            u64 wxx, wyn;
            lds_v2(wxx, wyn, wa + i * 16);
            acc0[i] = ffma2(wyn, s0, ffma2(wxx, ka0, acc0[i]));
            acc1[i] = ffma2(wyn, s1, ffma2(wxx, ka1, acc1[i]));
        }
        ka0 = kb0; ka1 = kb1; kb0 = kc0; kb1 = kc1;
    }

    float2* Gp = g_G1 + (size_t)(b * 32 + mg * 8) * 2048 + cs;
#pragma unroll
    for (int i = 0; i < 8; ++i) stg_v2(Gp + (size_t)i * 2048, acc0[i], acc1[i]);
}

// =====================================================================
// y2s: Y[b][(a*32+m)][s] = sum_c F[c,a] * G1[b*32+m][c*32+s]
// grid 512: 4 (b,m) per block; per (b,m): 64 thr = 16 s-pairs x 4 a-grps,
// thread tile 8a x 2s.
// =====================================================================
__global__ void __launch_bounds__(256) y2s_kernel(float2* __restrict__ Y) {
    __shared__ float4 Ft[2048];
    const int t = threadIdx.x;
#pragma unroll
    for (int i = 0; i < 8; ++i) Ft[t + 256 * i] = g_F4c[t + 256 * i];
    __syncthreads();

    const int bm = blockIdx.x * 4 + (t >> 6);
    const int b  = bm >> 5, m = bm & 31;
    const int sp = t & 15, ag = (t >> 4) & 3;
    const int s  = sp * 2;

    const float2* Gp = g_G1 + (size_t)bm * 2048 + s;       // + c*32
    const uint32_t fbase = saddr(Ft) + (uint32_t)(ag * 8) * 16;

    u64 acc0[8], acc1[8];
#pragma unroll
    for (int i = 0; i < 8; ++i) { acc0[i] = 0ull; acc1[i] = 0ull; }

    u64 ka0, ka1, kb0, kb1;
    ldg_v2(ka0, ka1, Gp);
    ldg_v2(kb0, kb1, Gp + 32);

#pragma unroll 2
    for (int c = 0; c < 64; ++c) {
        u64 kc0 = 0, kc1 = 0;
        if (c + 2 < 64) ldg_v2(kc0, kc1, Gp + (size_t)(c + 2) * 32);
        const u64 s0 = swap2(ka0), s1 = swap2(ka1);
        const uint32_t fa = fbase + (uint32_t)c * 512;
#pragma unroll
        for (int i = 0; i < 8; ++i) {
            u64 fxx, fyn;
            lds_v2(fxx, fyn, fa + i * 16);
            acc0[i] = ffma2(fyn, s0, ffma2(fxx, ka0, acc0[i]));
            acc1[i] = ffma2(fyn, s1, ffma2(fxx, ka1, acc1[i]));
        }
        ka0 = kb0; ka1 = kb1; kb0 = kc0; kb1 = kc1;
    }

#pragma unroll
    for (int i = 0; i < 8; ++i) {
        float2* yp = Y + (size_t)(b * 1024 + (ag * 8 + i) * 32 + m) * 32 + s;
        stg_v2(yp, acc0[i], acc1[i]);
    }
}

// =====================================================================
// y2n: Y[b][a*32 + r*4 + j][s] += sum_n conj(W[n, r*4+j]) * noise[b,r,n,x]
// x = a*32+s. grid 512 = (b,r); thread owns x-quad x0=t*4, 4 j.
// Pure 256MB DRAM stream + small RMW tail.
// =====================================================================
__global__ void __launch_bounds__(256) y2n_kernel(const float2* __restrict__ noise,
                                                  float2* __restrict__ Y) {
    __shared__ float4 Wn[256];   // [n*4+j]
    const int t = threadIdx.x;
    const int b = blockIdx.x >> 3, r = blockIdx.x & 7;
    Wn[t] = g_W4c[(t >> 2) * 32 + r * 4 + (t & 3)];
    __syncthreads();

    const int x0 = t * 4;
    const uint32_t wn = saddr(Wn);
    const float2* np = noise + (size_t)(b * 8 + r) * 65536 + x0;

    u64 acc[4][4];
#pragma unroll
    for (int j = 0; j < 4; ++j)
#pragma unroll
        for (int k = 0; k < 4; ++k) acc[j][k] = 0ull;

#pragma unroll 4
    for (int n = 0; n < 64; ++n) {
        u64 v0, v1, v2, v3;
        ldg_v2(v0, v1, np + (size_t)n * 1024);
        ldg_v2(v2, v3, np + (size_t)n * 1024 + 2);
        const u64 w0 = swap2(v0), w1 = swap2(v1), w2 = swap2(v2), w3 = swap2(v3);
#pragma unroll
        for (int j = 0; j < 4; ++j) {
            u64 wxx, wyn;
            lds_v2(wxx, wyn, wn + (uint32_t)((n * 4 + j) << 4));
            acc[j][0] = ffma2(wyn, w0, ffma2(wxx, v0, acc[j][0]));
            acc[j][1] = ffma2(wyn, w1, ffma2(wxx, v1, acc[j][1]));
            acc[j][2] = ffma2(wyn, w2, ffma2(wxx, v2, acc[j][2]));
            acc[j][3] = ffma2(wyn, w3, ffma2(wxx, v3, acc[j][3]));
        }
    }

    const int a = x0 >> 5, s = x0 & 31;
#pragma unroll
    for (int j = 0; j < 4; ++j) {
        float2* yp = Y + (size_t)(b * 1024 + a * 32 + r * 4 + j) * 32 + s;
        u64 y0, y1, y2, y3;
        ldg_v2_c(y0, y1, yp);
        ldg_v2_c(y2, y3, yp + 2);
        stg_v2(yp,     fadd2(y0, acc[j][0]), fadd2(y1, acc[j][1]));
        stg_v2(yp + 2, fadd2(y2, acc[j][2]), fadd2(y3, acc[j][3]));
    }
}

extern "C" void kernel_launch(void* const* d_in, const int* in_sizes, int n_in,
                              void* d_out, int out_size) {
    const float2* H     = (const float2*)d_in[0];  // (64,64,64,32,2) f32
    const float2* noise = (const float2*)d_in[1];  // (64,8,64,1024,2) f32
    const float*  kW    = (const float*)d_in[2];   // (64,32)
    const float*  kF    = (const float*)d_in[3];   // (64,32)
    const float2* K     = (const float2*)d_in[4];  // (4096,4096,2)

    float2* Phi = (float2*)d_out;                   // 1024*4096 complex
    float2* Y   = Phi + (size_t)1024 * 4096;        // 64*1024*32 complex

    setup_kernel<<<8, 256>>>(kW, kF);
    sA_kernel  <<<2048, 256>>>(K);
    y1_kernel  <<<1024, 256>>>(H);
    phiB_kernel<<<1024, 256>>>(Phi);
    y2s_kernel <<<512, 256>>>(Y);
    y2n_kernel <<<512, 256>>>(noise, Y);
}